// round 9
// baseline (speedup 1.0000x reference)
#include <cuda_runtime.h>

// TempoStateRNNCell: c_t = a_t * c_{t-1} + b_t along time (T=2048).
// inputs: (16, 2048, 4096) fp32, [:, :, :2048]=a, [:, :, 2048:]=b
// output: (16, 2048, 2048) fp32. Traffic floor 768 MB -> HBM-bound.
//
// Warp-autonomous cp.async pipelines: each warp owns a 32-unit slab and a
// private 12-stage smem ring (24 KB), loads exactly what it consumes, and
// synchronizes with __syncwarp only -- no CTA barriers, no cross-warp
// coupling. issue-before-wait keeps all 12 stages (24 KB/warp) pending.
// 512 CTAs x 64 threads (2 warps); smem = 48 KB static per CTA.

#define UNITS 2048
#define T_LEN 2048
#define BATCH 16
#define ROW   (2 * UNITS)     // floats per (batch, t) input row
#define WARPS 2               // warps per CTA
#define BLK   (WARPS * 32)
#define STEPS 8               // timesteps per stage
#define NST   12              // ring stages per warp
#define NSTG  (T_LEN / STEPS) // 256 stages

__device__ __forceinline__ void cp_async16(float* smem_dst, const float* gsrc) {
    unsigned saddr = (unsigned)__cvta_generic_to_shared(smem_dst);
    asm volatile("cp.async.cg.shared.global [%0], [%1], 16;\n"
                 :: "r"(saddr), "l"(gsrc));
}
__device__ __forceinline__ void cp_commit() {
    asm volatile("cp.async.commit_group;\n");
}
template <int N>
__device__ __forceinline__ void cp_wait() {
    asm volatile("cp.async.wait_group %0;\n" :: "n"(N));
}

__global__ void __launch_bounds__(BLK)
tempo_scan_kernel(const float* __restrict__ in, float* __restrict__ out)
{
    // [warp][stage][matrix a/b][step][unit-in-slab]
    __shared__ float ring[WARPS][NST][2][STEPS][32];   // 48 KB

    const int tid  = threadIdx.x;
    const int w    = tid >> 5;
    const int lane = tid & 31;

    const int batch = blockIdx.x >> 5;          // 16 batches
    const int slab  = blockIdx.x & 31;          // 32 slabs of 64 units
    const int unit0 = slab * BLK + w * 32;      // this warp's 32-unit slab

    const float* __restrict__ ga = in  + (size_t)batch * T_LEN * ROW + unit0;
    float*       __restrict__ go = out + (size_t)batch * T_LEN * UNITS + unit0 + lane;

    // Per-lane 16B chunks within this warp's stage (per matrix: 8 steps x
    // 128 B = 64 chunks; lane covers chunk lane and lane+32).
    const int sA0 = lane >> 3,        cA0 = (lane & 7) * 4;
    const int sA1 = (lane + 32) >> 3, cA1 = (lane & 7) * 4;   // steps 4..7

    auto issue = [&](int s) {
        if (s < NSTG) {
            const int slot = s % NST;
            const size_t tb = (size_t)s * STEPS;
            float (*st)[STEPS][32] = ring[w][slot];
            // matrix a
            cp_async16(&st[0][sA0][cA0], ga + (tb + sA0) * ROW + cA0);
            cp_async16(&st[0][sA1][cA1], ga + (tb + sA1) * ROW + cA1);
            // matrix b (offset +UNITS within the input row)
            cp_async16(&st[1][sA0][cA0], ga + (tb + sA0) * ROW + UNITS + cA0);
            cp_async16(&st[1][sA1][cA1], ga + (tb + sA1) * ROW + UNITS + cA1);
        }
        cp_commit();   // empty groups in the tail keep wait counts aligned
    };

    // Prime NST-1 stages
    for (int s = 0; s < NST - 1; ++s) issue(s);

    float c = 0.0f;   // c_0 = fma(a_0, 0, b_0) = b_0

    for (int s = 0; s < NSTG; ++s) {
        // All lanes finished reading slot (s-1)%NST (previous iteration)
        __syncwarp();
        // Refill that slot now -> full NST stages pending during the wait
        issue(s + NST - 1);

        cp_wait<NST - 1>();   // retires stage s (own groups)
        __syncwarp();         // cross-lane visibility of stage s data

        const int slot = s % NST;
        const float* da = &ring[w][slot][0][0][lane];
        const float* db = &ring[w][slot][1][0][lane];

        float ar[STEPS], br[STEPS];
        #pragma unroll
        for (int i = 0; i < STEPS; ++i) {
            ar[i] = da[i * 32];
            br[i] = db[i * 32];
        }

        const size_t tb = (size_t)s * STEPS;
        #pragma unroll
        for (int i = 0; i < STEPS; ++i) {
            c = fmaf(ar[i], c, br[i]);
            __stcs(go + (tb + i) * UNITS, c);
        }
    }
}

extern "C" void kernel_launch(void* const* d_in, const int* in_sizes, int n_in,
                              void* d_out, int out_size)
{
    const float* in  = (const float*)d_in[0];
    float*       out = (float*)d_out;

    const int grid = BATCH * (UNITS / BLK);   // 16 * 32 = 512 CTAs
    tempo_scan_kernel<<<grid, BLK>>>(in, out);
}

// round 10
// speedup vs baseline: 1.0528x; 1.0528x over previous
#include <cuda_runtime.h>

// TempoStateRNNCell: c_t = a_t * c_{t-1} + b_t along time (T=2048).
// inputs: (16, 2048, 4096) fp32, [:, :, :2048]=a, [:, :, 2048:]=b
// output: (16, 2048, 2048) fp32. Traffic floor 768 MB -> HBM-bound.
//
// Tuned R8: cp.async SMEM ring, 6 stages x 16 timesteps (96 KB/CTA,
// ~80 KB pending). Halved iteration count (128 vs 256) cuts barrier /
// wait / loop overhead; load pattern keeps R8's contiguous 512B-per-
// warp-op spans. 256 CTAs x 128 threads, 1 thread per (batch, unit).

#define UNITS 2048
#define T_LEN 2048
#define BATCH 16
#define ROW   (2 * UNITS)            // 4096 floats per (batch, t) input row
#define BLK   128                    // threads = units per CTA
#define STEPS 16                     // timesteps per stage
#define NST   6                      // ring stages
#define STAGE_FLOATS (STEPS * BLK)   // 2048 floats (8 KB) per matrix per stage
#define SMEM_BYTES (2 * NST * STAGE_FLOATS * 4)   // 96 KB
#define NSTG  (T_LEN / STEPS)        // 128 stages

__device__ __forceinline__ void cp_async16(float* smem_dst, const float* gsrc) {
    unsigned saddr = (unsigned)__cvta_generic_to_shared(smem_dst);
    asm volatile("cp.async.cg.shared.global [%0], [%1], 16;\n"
                 :: "r"(saddr), "l"(gsrc));
}
__device__ __forceinline__ void cp_commit() {
    asm volatile("cp.async.commit_group;\n");
}
template <int N>
__device__ __forceinline__ void cp_wait() {
    asm volatile("cp.async.wait_group %0;\n" :: "n"(N));
}

__global__ void __launch_bounds__(BLK)
tempo_scan_kernel(const float* __restrict__ in, float* __restrict__ out)
{
    extern __shared__ float smem[];
    float* sa = smem;                        // [NST][STEPS][BLK]
    float* sb = smem + NST * STAGE_FLOATS;   // [NST][STEPS][BLK]

    const int tid   = threadIdx.x;
    const int batch = blockIdx.x >> 4;
    const int unit0 = (blockIdx.x & 15) * BLK;

    const float* __restrict__ gin = in + (size_t)batch * T_LEN * ROW + unit0;
    float* __restrict__ gout = out + (size_t)batch * T_LEN * UNITS + unit0 + tid;

    // Chunk mapping per matrix per stage: 16 steps x 32 chunks(16B) = 512
    // chunks / 128 threads = 4 per thread. Chunk c = tid + 128k:
    //   step = (tid>>5) + 4k, col = (tid&31)*4  -> each warp-op spans a
    //   contiguous 512 B of one row (the R8 pattern that beat R9's).
    const int stp = tid >> 5;            // base step (0..3)
    const int col = (tid & 31) * 4;      // float offset within 128-unit slab

    auto issue = [&](int s) {
        if (s < NSTG) {
            const int slot = s % NST;
            const size_t tb = (size_t)s * STEPS;
            float* da = sa + slot * STAGE_FLOATS;
            float* db = sb + slot * STAGE_FLOATS;
            #pragma unroll
            for (int k = 0; k < 4; ++k) {
                const int st = stp + 4 * k;
                cp_async16(da + st * BLK + col, gin + (tb + st) * ROW + col);
                cp_async16(db + st * BLK + col, gin + (tb + st) * ROW + UNITS + col);
            }
        }
        cp_commit();   // empty groups in the tail keep wait counts aligned
    };

    // Prime NST-1 stages
    for (int s = 0; s < NST - 1; ++s) issue(s);

    float c = 0.0f;   // c_0 = fma(a_0, 0, b_0) = b_0

    for (int s = 0; s < NSTG; ++s) {
        cp_wait<NST - 2>();   // own groups through stage s retired
        __syncthreads();      // everyone's stage s visible; fences slot reuse

        // Refill slot (s-1)%NST (consumed last iteration, ordered above)
        issue(s + NST - 1);

        const int slot = s % NST;
        const float* da = sa + slot * STAGE_FLOATS + tid;
        const float* db = sb + slot * STAGE_FLOATS + tid;

        float ar[STEPS], br[STEPS];
        #pragma unroll
        for (int i = 0; i < STEPS; ++i) {
            ar[i] = da[i * BLK];
            br[i] = db[i * BLK];
        }

        const size_t tb = (size_t)s * STEPS;
        #pragma unroll
        for (int i = 0; i < STEPS; ++i) {
            c = fmaf(ar[i], c, br[i]);
            __stcs(gout + (tb + i) * UNITS, c);
        }
    }
}

extern "C" void kernel_launch(void* const* d_in, const int* in_sizes, int n_in,
                              void* d_out, int out_size)
{
    const float* in  = (const float*)d_in[0];
    float*       out = (float*)d_out;

    // Raise dynamic smem limit (attribute, not an allocation)
    cudaFuncSetAttribute(tempo_scan_kernel,
                         cudaFuncAttributeMaxDynamicSharedMemorySize, SMEM_BYTES);

    const int grid = BATCH * (UNITS / BLK);   // 256 CTAs
    tempo_scan_kernel<<<grid, BLK, SMEM_BYTES>>>(in, out);
}

// round 11
// speedup vs baseline: 1.0534x; 1.0005x over previous
#include <cuda_runtime.h>

// TempoStateRNNCell: c_t = a_t * c_{t-1} + b_t along time (T=2048).
// inputs: (16, 2048, 4096) fp32, [:, :, :2048]=a, [:, :, 2048:]=b
// output: (16, 2048, 2048) fp32. Traffic floor 768 MB -> HBM-bound.
//
// cp.async SMEM ring, 6 stages x 16 timesteps (96 KB/CTA). R11: add
// .L2::256B prefetch to every cp.async -- each line is fetched anyway
// (contiguous spans), but the L2 prefetcher presents deeper, smoother
// read bursts to the DRAM controller. 256 CTAs x 128 threads.

#define UNITS 2048
#define T_LEN 2048
#define BATCH 16
#define ROW   (2 * UNITS)            // 4096 floats per (batch, t) input row
#define BLK   128                    // threads = units per CTA
#define STEPS 16                     // timesteps per stage
#define NST   6                      // ring stages
#define STAGE_FLOATS (STEPS * BLK)   // 2048 floats (8 KB) per matrix per stage
#define SMEM_BYTES (2 * NST * STAGE_FLOATS * 4)   // 96 KB
#define NSTG  (T_LEN / STEPS)        // 128 stages

__device__ __forceinline__ void cp_async16(float* smem_dst, const float* gsrc) {
    unsigned saddr = (unsigned)__cvta_generic_to_shared(smem_dst);
    asm volatile("cp.async.cg.shared.global.L2::256B [%0], [%1], 16;\n"
                 :: "r"(saddr), "l"(gsrc));
}
__device__ __forceinline__ void cp_commit() {
    asm volatile("cp.async.commit_group;\n");
}
template <int N>
__device__ __forceinline__ void cp_wait() {
    asm volatile("cp.async.wait_group %0;\n" :: "n"(N));
}

__global__ void __launch_bounds__(BLK)
tempo_scan_kernel(const float* __restrict__ in, float* __restrict__ out)
{
    extern __shared__ float smem[];
    float* sa = smem;                        // [NST][STEPS][BLK]
    float* sb = smem + NST * STAGE_FLOATS;   // [NST][STEPS][BLK]

    const int tid   = threadIdx.x;
    const int batch = blockIdx.x >> 4;
    const int unit0 = (blockIdx.x & 15) * BLK;

    const float* __restrict__ gin = in + (size_t)batch * T_LEN * ROW + unit0;
    float* __restrict__ gout = out + (size_t)batch * T_LEN * UNITS + unit0 + tid;

    // 4 chunks (16B) per thread per matrix per stage; each warp-op spans a
    // contiguous 512 B of one row.
    const int stp = tid >> 5;            // base step (0..3)
    const int col = (tid & 31) * 4;      // float offset within 128-unit slab

    auto issue = [&](int s) {
        if (s < NSTG) {
            const int slot = s % NST;
            const size_t tb = (size_t)s * STEPS;
            float* da = sa + slot * STAGE_FLOATS;
            float* db = sb + slot * STAGE_FLOATS;
            #pragma unroll
            for (int k = 0; k < 4; ++k) {
                const int st = stp + 4 * k;
                cp_async16(da + st * BLK + col, gin + (tb + st) * ROW + col);
                cp_async16(db + st * BLK + col, gin + (tb + st) * ROW + UNITS + col);
            }
        }
        cp_commit();   // empty groups in the tail keep wait counts aligned
    };

    // Prime NST-1 stages
    for (int s = 0; s < NST - 1; ++s) issue(s);

    float c = 0.0f;   // c_0 = fma(a_0, 0, b_0) = b_0

    for (int s = 0; s < NSTG; ++s) {
        cp_wait<NST - 2>();   // own groups through stage s retired
        __syncthreads();      // everyone's stage s visible; fences slot reuse

        // Refill slot (s-1)%NST (consumed last iteration, ordered above)
        issue(s + NST - 1);

        const int slot = s % NST;
        const float* da = sa + slot * STAGE_FLOATS + tid;
        const float* db = sb + slot * STAGE_FLOATS + tid;

        float ar[STEPS], br[STEPS];
        #pragma unroll
        for (int i = 0; i < STEPS; ++i) {
            ar[i] = da[i * BLK];
            br[i] = db[i * BLK];
        }

        const size_t tb = (size_t)s * STEPS;
        #pragma unroll
        for (int i = 0; i < STEPS; ++i) {
            c = fmaf(ar[i], c, br[i]);
            __stcs(gout + (tb + i) * UNITS, c);
        }
    }
}

extern "C" void kernel_launch(void* const* d_in, const int* in_sizes, int n_in,
                              void* d_out, int out_size)
{
    const float* in  = (const float*)d_in[0];
    float*       out = (float*)d_out;

    // Raise dynamic smem limit (attribute, not an allocation)
    cudaFuncSetAttribute(tempo_scan_kernel,
                         cudaFuncAttributeMaxDynamicSharedMemorySize, SMEM_BYTES);

    const int grid = BATCH * (UNITS / BLK);   // 256 CTAs
    tempo_scan_kernel<<<grid, BLK, SMEM_BYTES>>>(in, out);
}